// round 2
// baseline (speedup 1.0000x reference)
#include <cuda_runtime.h>
#include <cuda_bf16.h>
#include <cstdint>

// ---------------------------------------------------------------------------
// Problem constants
// ---------------------------------------------------------------------------
#define NTOK 4096
#define CDIM 1024
#define NHEAD 16
#define HDIM 64
#define MDIM 4096
#define QKVDIM 3072

// ---------------------------------------------------------------------------
// Scratch (device globals — no allocations allowed)
// ---------------------------------------------------------------------------
__device__ float g_h  [(size_t)NTOK * CDIM];    // rmsnorm1 output
__device__ float g_qkv[(size_t)NTOK * QKVDIM];  // qkv projection
__device__ float g_o  [(size_t)NTOK * CDIM];    // attention output
__device__ float g_x1 [(size_t)NTOK * CDIM];    // x + o @ w_o
__device__ float g_h2 [(size_t)NTOK * CDIM];    // rmsnorm2 output
__device__ float g_t  [(size_t)NTOK * MDIM];    // gelu(h2 @ w1)

// ---------------------------------------------------------------------------
// RMSNorm: one block per row (1024 floats), 256 threads, float4 per thread
// ---------------------------------------------------------------------------
__global__ __launch_bounds__(256) void rmsnorm_kernel(
    const float* __restrict__ x, const float* __restrict__ g,
    float* __restrict__ out)
{
    const int row = blockIdx.x;
    const int tid = threadIdx.x;
    const float4 v = ((const float4*)(x + (size_t)row * CDIM))[tid];
    float ss = v.x * v.x + v.y * v.y + v.z * v.z + v.w * v.w;
    #pragma unroll
    for (int o = 16; o; o >>= 1) ss += __shfl_xor_sync(0xffffffffu, ss, o);
    __shared__ float wsum[8];
    if ((tid & 31) == 0) wsum[tid >> 5] = ss;
    __syncthreads();
    float tot = wsum[0] + wsum[1] + wsum[2] + wsum[3]
              + wsum[4] + wsum[5] + wsum[6] + wsum[7];
    const float inv = rsqrtf(tot * (1.0f / (float)CDIM) + 1e-6f);
    const float4 gv = ((const float4*)g)[tid];
    float4 ov;
    ov.x = v.x * inv * gv.x;
    ov.y = v.y * inv * gv.y;
    ov.z = v.z * inv * gv.z;
    ov.w = v.w * inv * gv.w;
    ((float4*)(out + (size_t)row * CDIM))[tid] = ov;
}

// ---------------------------------------------------------------------------
// SGEMM: C[M,N] = A[M,K] @ B[K,N]   (row-major, all dims multiples of 128)
// 128x128 tile, BK=8, 256 threads, 8x8 per thread.
// MODE 0: C = acc;  MODE 1: C = acc + R;  MODE 2: C = gelu(acc)
// ---------------------------------------------------------------------------
__device__ __forceinline__ float gelu_tanh(float x) {
    const float u = 0.7978845608028654f * (x + 0.044715f * x * x * x);
    return 0.5f * x * (1.0f + tanhf(u));
}

template <int MODE>
__global__ __launch_bounds__(256) void sgemm_kernel(
    const float* __restrict__ A, const float* __restrict__ B,
    const float* __restrict__ R, float* __restrict__ C,
    int M, int N, int K)
{
    __shared__ float As[8][128];
    __shared__ float Bs[8][128];

    const int tid = threadIdx.x;
    const int bm = blockIdx.y * 128;
    const int bn = blockIdx.x * 128;

    const int arow = tid >> 1;            // 0..127
    const int acol = (tid & 1) * 4;       // 0 or 4
    const int brow = tid >> 5;            // 0..7
    const int bcol = (tid & 31) * 4;      // 0..124

    const float* Ap = A + (size_t)(bm + arow) * K + acol;
    const float* Bp = B + (size_t)brow * N + bn + bcol;

    const int ty = tid >> 4;              // 0..15
    const int tx = tid & 15;              // 0..15

    float acc[8][8];
    #pragma unroll
    for (int i = 0; i < 8; i++)
        #pragma unroll
        for (int j = 0; j < 8; j++) acc[i][j] = 0.0f;

    for (int k0 = 0; k0 < K; k0 += 8) {
        const float4 av = *(const float4*)Ap;  Ap += 8;
        const float4 bv = *(const float4*)Bp;  Bp += (size_t)8 * N;

        As[acol + 0][arow] = av.x;
        As[acol + 1][arow] = av.y;
        As[acol + 2][arow] = av.z;
        As[acol + 3][arow] = av.w;
        *(float4*)&Bs[brow][bcol] = bv;
        __syncthreads();

        #pragma unroll
        for (int k = 0; k < 8; k++) {
            float a[8], b[8];
            *(float4*)&a[0] = *(const float4*)&As[k][ty * 8];
            *(float4*)&a[4] = *(const float4*)&As[k][ty * 8 + 4];
            *(float4*)&b[0] = *(const float4*)&Bs[k][tx * 8];
            *(float4*)&b[4] = *(const float4*)&Bs[k][tx * 8 + 4];
            #pragma unroll
            for (int i = 0; i < 8; i++)
                #pragma unroll
                for (int j = 0; j < 8; j++)
                    acc[i][j] += a[i] * b[j];
        }
        __syncthreads();
    }

    #pragma unroll
    for (int i = 0; i < 8; i++) {
        const size_t row = (size_t)(bm + ty * 8 + i);
        float* Cp = C + row * N + bn + tx * 8;
        #pragma unroll
        for (int j = 0; j < 8; j += 4) {
            float4 v = make_float4(acc[i][j], acc[i][j + 1],
                                   acc[i][j + 2], acc[i][j + 3]);
            if (MODE == 1) {
                const float4 r4 = *(const float4*)(R + row * N + bn + tx * 8 + j);
                v.x += r4.x; v.y += r4.y; v.z += r4.z; v.w += r4.w;
            }
            if (MODE == 2) {
                v.x = gelu_tanh(v.x); v.y = gelu_tanh(v.y);
                v.z = gelu_tanh(v.z); v.w = gelu_tanh(v.w);
            }
            *(float4*)(Cp + j) = v;
        }
    }
}

// ---------------------------------------------------------------------------
// Flash attention (fp32, no mask). qkv layout: [n][3][H][D] row-major.
// Block: 256 threads handles 64 queries of one head; loops over 64-key tiles.
// smem: Qs[64][64], Ks[64][64] (d-major), Vs[64][64], Ps[64][64] = 64 KB dyn.
// ---------------------------------------------------------------------------
__global__ __launch_bounds__(256) void flash_kernel(
    const float* __restrict__ qkv, float* __restrict__ o)
{
    extern __shared__ float sm[];
    float* Qs = sm;               // [r][d]
    float* Ks = sm + 4096;        // [d][key]   (transposed)
    float* Vs = sm + 8192;        // [key][d]
    float* Ps = sm + 12288;       // [r][key]

    const int tid = threadIdx.x;
    const int ty = tid >> 4;          // 0..15
    const int tx = tid & 15;          // 0..15
    const int lr = tid >> 4;          // load row group
    const int lc = (tid & 15) * 4;    // load col (float4)
    const int h  = blockIdx.y;
    const int q0 = blockIdx.x * 64;

    // Load Q tile (pre-scaled by 1/sqrt(D))
    {
        const float* Qp = qkv + (size_t)q0 * QKVDIM + h * HDIM;
        #pragma unroll
        for (int s = 0; s < 4; s++) {
            const int r = lr + s * 16;
            float4 v = *(const float4*)(Qp + (size_t)r * QKVDIM + lc);
            v.x *= 0.125f; v.y *= 0.125f; v.z *= 0.125f; v.w *= 0.125f;
            *(float4*)(Qs + r * 64 + lc) = v;
        }
    }

    float m_i[4], l_i[4], acc[4][4];
    #pragma unroll
    for (int i = 0; i < 4; i++) {
        m_i[i] = -1e30f; l_i[i] = 0.0f;
        #pragma unroll
        for (int j = 0; j < 4; j++) acc[i][j] = 0.0f;
    }

    for (int k0 = 0; k0 < NTOK; k0 += 64) {
        // Load K (transposed to d-major) and V (natural)
        const float* Kp = qkv + (size_t)k0 * QKVDIM + CDIM + h * HDIM;
        const float* Vp = Kp + CDIM;
        #pragma unroll
        for (int s = 0; s < 4; s++) {
            const int r = lr + s * 16;
            const float4 kv = *(const float4*)(Kp + (size_t)r * QKVDIM + lc);
            Ks[(lc + 0) * 64 + r] = kv.x;
            Ks[(lc + 1) * 64 + r] = kv.y;
            Ks[(lc + 2) * 64 + r] = kv.z;
            Ks[(lc + 3) * 64 + r] = kv.w;
            const float4 vv = *(const float4*)(Vp + (size_t)r * QKVDIM + lc);
            *(float4*)(Vs + r * 64 + lc) = vv;
        }
        __syncthreads();

        // S = Q K^T (scaled already)
        float sv[4][4];
        #pragma unroll
        for (int i = 0; i < 4; i++)
            #pragma unroll
            for (int j = 0; j < 4; j++) sv[i][j] = 0.0f;

        #pragma unroll 8
        for (int d = 0; d < 64; d++) {
            const float4 kk = *(const float4*)(Ks + d * 64 + tx * 4);
            const float qa = Qs[(ty * 4 + 0) * 64 + d];
            const float qb = Qs[(ty * 4 + 1) * 64 + d];
            const float qc = Qs[(ty * 4 + 2) * 64 + d];
            const float qd = Qs[(ty * 4 + 3) * 64 + d];
            sv[0][0] += qa * kk.x; sv[0][1] += qa * kk.y; sv[0][2] += qa * kk.z; sv[0][3] += qa * kk.w;
            sv[1][0] += qb * kk.x; sv[1][1] += qb * kk.y; sv[1][2] += qb * kk.z; sv[1][3] += qb * kk.w;
            sv[2][0] += qc * kk.x; sv[2][1] += qc * kk.y; sv[2][2] += qc * kk.z; sv[2][3] += qc * kk.w;
            sv[3][0] += qd * kk.x; sv[3][1] += qd * kk.y; sv[3][2] += qd * kk.z; sv[3][3] += qd * kk.w;
        }

        // Online softmax (row = ty*4+i; 16 tx lanes share each row)
        #pragma unroll
        for (int i = 0; i < 4; i++) {
            float mx = fmaxf(fmaxf(sv[i][0], sv[i][1]), fmaxf(sv[i][2], sv[i][3]));
            mx = fmaxf(mx, __shfl_xor_sync(0xffffffffu, mx, 1, 16));
            mx = fmaxf(mx, __shfl_xor_sync(0xffffffffu, mx, 2, 16));
            mx = fmaxf(mx, __shfl_xor_sync(0xffffffffu, mx, 4, 16));
            mx = fmaxf(mx, __shfl_xor_sync(0xffffffffu, mx, 8, 16));
            const float mnew = fmaxf(m_i[i], mx);
            const float corr = __expf(m_i[i] - mnew);
            m_i[i] = mnew;
            float rs = 0.0f;
            #pragma unroll
            for (int j = 0; j < 4; j++) {
                sv[i][j] = __expf(sv[i][j] - mnew);
                rs += sv[i][j];
            }
            rs += __shfl_xor_sync(0xffffffffu, rs, 1, 16);
            rs += __shfl_xor_sync(0xffffffffu, rs, 2, 16);
            rs += __shfl_xor_sync(0xffffffffu, rs, 4, 16);
            rs += __shfl_xor_sync(0xffffffffu, rs, 8, 16);
            l_i[i] = l_i[i] * corr + rs;
            #pragma unroll
            for (int j = 0; j < 4; j++) acc[i][j] *= corr;
            *(float4*)(Ps + (ty * 4 + i) * 64 + tx * 4) =
                make_float4(sv[i][0], sv[i][1], sv[i][2], sv[i][3]);
        }
        __syncthreads();

        // O += P V
        #pragma unroll 8
        for (int k2 = 0; k2 < 64; k2++) {
            const float4 vv = *(const float4*)(Vs + k2 * 64 + tx * 4);
            const float p0 = Ps[(ty * 4 + 0) * 64 + k2];
            const float p1 = Ps[(ty * 4 + 1) * 64 + k2];
            const float p2 = Ps[(ty * 4 + 2) * 64 + k2];
            const float p3 = Ps[(ty * 4 + 3) * 64 + k2];
            acc[0][0] += p0 * vv.x; acc[0][1] += p0 * vv.y; acc[0][2] += p0 * vv.z; acc[0][3] += p0 * vv.w;
            acc[1][0] += p1 * vv.x; acc[1][1] += p1 * vv.y; acc[1][2] += p1 * vv.z; acc[1][3] += p1 * vv.w;
            acc[2][0] += p2 * vv.x; acc[2][1] += p2 * vv.y; acc[2][2] += p2 * vv.z; acc[2][3] += p2 * vv.w;
            acc[3][0] += p3 * vv.x; acc[3][1] += p3 * vv.y; acc[3][2] += p3 * vv.z; acc[3][3] += p3 * vv.w;
        }
        __syncthreads();
    }

    // Write O (o layout: [n][h*64+d])
    #pragma unroll
    for (int i = 0; i < 4; i++) {
        const float inv = 1.0f / l_i[i];
        const float4 ov = make_float4(acc[i][0] * inv, acc[i][1] * inv,
                                      acc[i][2] * inv, acc[i][3] * inv);
        *(float4*)(o + (size_t)(q0 + ty * 4 + i) * CDIM + h * HDIM + tx * 4) = ov;
    }
}

// ---------------------------------------------------------------------------
// Launcher
// ---------------------------------------------------------------------------
extern "C" void kernel_launch(void* const* d_in, const int* in_sizes, int n_in,
                              void* d_out, int out_size)
{
    const float* x     = (const float*)d_in[0];
    const float* g1    = (const float*)d_in[1];
    const float* g2    = (const float*)d_in[2];
    const float* w_qkv = (const float*)d_in[3];
    const float* w_o   = (const float*)d_in[4];
    const float* w1    = (const float*)d_in[5];
    const float* w2    = (const float*)d_in[6];
    float* out = (float*)d_out;

    float *h, *qkv, *o, *x1, *h2, *t;
    cudaGetSymbolAddress((void**)&h,   g_h);
    cudaGetSymbolAddress((void**)&qkv, g_qkv);
    cudaGetSymbolAddress((void**)&o,   g_o);
    cudaGetSymbolAddress((void**)&x1,  g_x1);
    cudaGetSymbolAddress((void**)&h2,  g_h2);
    cudaGetSymbolAddress((void**)&t,   g_t);

    cudaFuncSetAttribute(flash_kernel,
                         cudaFuncAttributeMaxDynamicSharedMemorySize, 65536);

    // 1) h = rmsnorm(x, g1)
    rmsnorm_kernel<<<NTOK, 256>>>(x, g1, h);

    // 2) qkv = h @ w_qkv          (4096 x 3072, K=1024)
    sgemm_kernel<0><<<dim3(QKVDIM / 128, NTOK / 128), 256>>>(
        h, w_qkv, nullptr, qkv, NTOK, QKVDIM, CDIM);

    // 3) o = attention(qkv)
    flash_kernel<<<dim3(NTOK / 64, NHEAD), 256, 65536>>>(qkv, o);

    // 4) x1 = x + o @ w_o         (4096 x 1024, K=1024)
    sgemm_kernel<1><<<dim3(CDIM / 128, NTOK / 128), 256>>>(
        o, w_o, x, x1, NTOK, CDIM, CDIM);

    // 5) h2 = rmsnorm(x1, g2)
    rmsnorm_kernel<<<NTOK, 256>>>(x1, g2, h2);

    // 6) t = gelu(h2 @ w1)        (4096 x 4096, K=1024)
    sgemm_kernel<2><<<dim3(MDIM / 128, NTOK / 128), 256>>>(
        h2, w1, nullptr, t, NTOK, MDIM, CDIM);

    // 7) out = x1 + t @ w2        (4096 x 1024, K=4096)
    sgemm_kernel<1><<<dim3(CDIM / 128, NTOK / 128), 256>>>(
        t, w2, x1, out, NTOK, CDIM, MDIM);
}

// round 3
// speedup vs baseline: 1.5365x; 1.5365x over previous
#include <cuda_runtime.h>
#include <cuda_bf16.h>
#include <cstdint>

// ---------------------------------------------------------------------------
// Problem constants
// ---------------------------------------------------------------------------
#define NTOK 4096
#define CDIM 1024
#define NHEAD 16
#define HDIM 64
#define MDIM 4096
#define QKVDIM 3072

// ---------------------------------------------------------------------------
// Scratch (device globals — no allocations allowed)
// ---------------------------------------------------------------------------
__device__ float g_h  [(size_t)NTOK * CDIM];    // rmsnorm1 output
__device__ float g_qkv[(size_t)NTOK * QKVDIM];  // qkv projection
__device__ float g_o  [(size_t)NTOK * CDIM];    // attention output
__device__ float g_x1 [(size_t)NTOK * CDIM];    // x + o @ w_o
__device__ float g_h2 [(size_t)NTOK * CDIM];    // rmsnorm2 output
__device__ float g_t  [(size_t)NTOK * MDIM];    // gelu(h2 @ w1)

// ---------------------------------------------------------------------------
// RMSNorm: one block per row (1024 floats), 256 threads, float4 per thread
// ---------------------------------------------------------------------------
__global__ __launch_bounds__(256) void rmsnorm_kernel(
    const float* __restrict__ x, const float* __restrict__ g,
    float* __restrict__ out)
{
    const int row = blockIdx.x;
    const int tid = threadIdx.x;
    const float4 v = ((const float4*)(x + (size_t)row * CDIM))[tid];
    float ss = v.x * v.x + v.y * v.y + v.z * v.z + v.w * v.w;
    #pragma unroll
    for (int o = 16; o; o >>= 1) ss += __shfl_xor_sync(0xffffffffu, ss, o);
    __shared__ float wsum[8];
    if ((tid & 31) == 0) wsum[tid >> 5] = ss;
    __syncthreads();
    float tot = wsum[0] + wsum[1] + wsum[2] + wsum[3]
              + wsum[4] + wsum[5] + wsum[6] + wsum[7];
    const float inv = rsqrtf(tot * (1.0f / (float)CDIM) + 1e-6f);
    const float4 gv = ((const float4*)g)[tid];
    float4 ov;
    ov.x = v.x * inv * gv.x;
    ov.y = v.y * inv * gv.y;
    ov.z = v.z * inv * gv.z;
    ov.w = v.w * inv * gv.w;
    ((float4*)(out + (size_t)row * CDIM))[tid] = ov;
}

// ---------------------------------------------------------------------------
// TF32 tensor-core GEMM: C[M,N] = A[M,K] @ B[K,N] (row-major)
// 128x128x16 CTA tile, 8 warps, warp tile 64x32, mma.m16n8k8.tf32,
// cp.async double buffering.
// MODE 0: C = acc;  MODE 1: C = acc + R;  MODE 2: C = gelu(acc)
// ---------------------------------------------------------------------------
__device__ __forceinline__ float gelu_tanh(float x) {
    const float u = 0.7978845608028654f * (x + 0.044715f * x * x * x);
    return 0.5f * x * (1.0f + tanhf(u));
}

__device__ __forceinline__ uint32_t cvt_tf32(float x) {
    uint32_t r;
    asm("cvt.rna.tf32.f32 %0, %1;" : "=r"(r) : "f"(x));
    return r;
}

__device__ __forceinline__ void mma_tf32(float* c, const uint32_t* a,
                                         const uint32_t* b) {
    asm volatile(
        "mma.sync.aligned.m16n8k8.row.col.f32.tf32.tf32.f32 "
        "{%0,%1,%2,%3}, {%4,%5,%6,%7}, {%8,%9}, {%0,%1,%2,%3};"
        : "+f"(c[0]), "+f"(c[1]), "+f"(c[2]), "+f"(c[3])
        : "r"(a[0]), "r"(a[1]), "r"(a[2]), "r"(a[3]),
          "r"(b[0]), "r"(b[1]));
}

__device__ __forceinline__ void cp16(void* smem, const void* gmem) {
    uint32_t s = (uint32_t)__cvta_generic_to_shared(smem);
    asm volatile("cp.async.cg.shared.global [%0], [%1], 16;"
                 :: "r"(s), "l"(gmem));
}

#define AST 20    // As row stride (16 + pad 4) -> conflict-free frag reads
#define BST 136   // Bs row stride (128 + pad 8)

template <int MODE>
__global__ __launch_bounds__(256) void tgemm_kernel(
    const float* __restrict__ A, const float* __restrict__ B,
    const float* __restrict__ R, float* __restrict__ C,
    int M, int N, int K)
{
    __shared__ float As[2][128 * AST];
    __shared__ float Bs[2][16 * BST];

    const int tid  = threadIdx.x;
    const int bm   = blockIdx.y * 128;
    const int bn   = blockIdx.x * 128;
    const int warp = tid >> 5;
    const int lane = tid & 31;
    const int wm   = (warp >> 2) << 6;   // 0 / 64
    const int wn   = (warp & 3) << 5;    // 0,32,64,96
    const int lr   = lane >> 2;          // 0..7
    const int lc   = lane & 3;           // 0..3

    float acc[4][4][4];
    #pragma unroll
    for (int mt = 0; mt < 4; mt++)
        #pragma unroll
        for (int nt = 0; nt < 4; nt++)
            #pragma unroll
            for (int i = 0; i < 4; i++) acc[mt][nt][i] = 0.0f;

    // --- async copy of one 128x16 A tile + 16x128 B tile ---
    auto prefetch = [&](int buf, int k0) {
        #pragma unroll
        for (int r = 0; r < 2; r++) {
            const int idx = tid + (r << 8);       // 0..511
            const int am  = idx >> 2;             // 0..127
            const int akq = (idx & 3) << 2;       // 0,4,8,12
            cp16(&As[buf][am * AST + akq],
                 A + (size_t)(bm + am) * K + k0 + akq);
            const int bk  = idx >> 5;             // 0..15
            const int bnq = (idx & 31) << 2;      // 0..124
            cp16(&Bs[buf][bk * BST + bnq],
                 B + (size_t)(k0 + bk) * N + bn + bnq);
        }
        asm volatile("cp.async.commit_group;");
    };

    prefetch(0, 0);
    int buf = 0;

    for (int k0 = 0; k0 < K; k0 += 16) {
        asm volatile("cp.async.wait_group 0;");
        __syncthreads();
        if (k0 + 16 < K) prefetch(buf ^ 1, k0 + 16);

        #pragma unroll
        for (int ks = 0; ks < 2; ks++) {
            uint32_t af[4][4], bf[4][2];
            #pragma unroll
            for (int mt = 0; mt < 4; mt++) {
                const float* ap =
                    &As[buf][(wm + mt * 16 + lr) * AST + ks * 8 + lc];
                af[mt][0] = cvt_tf32(ap[0]);
                af[mt][1] = cvt_tf32(ap[8 * AST]);
                af[mt][2] = cvt_tf32(ap[4]);
                af[mt][3] = cvt_tf32(ap[8 * AST + 4]);
            }
            #pragma unroll
            for (int nt = 0; nt < 4; nt++) {
                const float* bp =
                    &Bs[buf][(ks * 8 + lc) * BST + wn + nt * 8 + lr];
                bf[nt][0] = cvt_tf32(bp[0]);
                bf[nt][1] = cvt_tf32(bp[4 * BST]);
            }
            #pragma unroll
            for (int mt = 0; mt < 4; mt++)
                #pragma unroll
                for (int nt = 0; nt < 4; nt++)
                    mma_tf32(acc[mt][nt], af[mt], bf[nt]);
        }
        __syncthreads();
        buf ^= 1;
    }

    // --- epilogue ---
    #pragma unroll
    for (int mt = 0; mt < 4; mt++) {
        const int row0 = bm + wm + mt * 16 + lr;
        #pragma unroll
        for (int nt = 0; nt < 4; nt++) {
            const int col = bn + wn + nt * 8 + lc * 2;
            #pragma unroll
            for (int half = 0; half < 2; half++) {
                const size_t row = (size_t)(row0 + half * 8);
                float2 v = make_float2(acc[mt][nt][half * 2],
                                       acc[mt][nt][half * 2 + 1]);
                if (MODE == 1) {
                    const float2 r2 = *(const float2*)(R + row * N + col);
                    v.x += r2.x; v.y += r2.y;
                }
                if (MODE == 2) {
                    v.x = gelu_tanh(v.x);
                    v.y = gelu_tanh(v.y);
                }
                *(float2*)(C + row * N + col) = v;
            }
        }
    }
}

// ---------------------------------------------------------------------------
// Flash attention (fp32). qkv layout: [n][3][H][D] row-major.
// Block: 256 threads handles 64 queries of one head; loops over 64-key tiles.
// ---------------------------------------------------------------------------
__global__ __launch_bounds__(256) void flash_kernel(
    const float* __restrict__ qkv, float* __restrict__ o)
{
    extern __shared__ float sm[];
    float* Qs = sm;               // [r][d]
    float* Ks = sm + 4096;        // [d][key]   (transposed)
    float* Vs = sm + 8192;        // [key][d]
    float* Ps = sm + 12288;       // [r][key]

    const int tid = threadIdx.x;
    const int ty = tid >> 4;          // 0..15
    const int tx = tid & 15;          // 0..15
    const int lr = tid >> 4;
    const int lc = (tid & 15) * 4;
    const int h  = blockIdx.y;
    const int q0 = blockIdx.x * 64;

    {
        const float* Qp = qkv + (size_t)q0 * QKVDIM + h * HDIM;
        #pragma unroll
        for (int s = 0; s < 4; s++) {
            const int r = lr + s * 16;
            float4 v = *(const float4*)(Qp + (size_t)r * QKVDIM + lc);
            v.x *= 0.125f; v.y *= 0.125f; v.z *= 0.125f; v.w *= 0.125f;
            *(float4*)(Qs + r * 64 + lc) = v;
        }
    }

    float m_i[4], l_i[4], acc[4][4];
    #pragma unroll
    for (int i = 0; i < 4; i++) {
        m_i[i] = -1e30f; l_i[i] = 0.0f;
        #pragma unroll
        for (int j = 0; j < 4; j++) acc[i][j] = 0.0f;
    }

    for (int k0 = 0; k0 < NTOK; k0 += 64) {
        const float* Kp = qkv + (size_t)k0 * QKVDIM + CDIM + h * HDIM;
        const float* Vp = Kp + CDIM;
        #pragma unroll
        for (int s = 0; s < 4; s++) {
            const int r = lr + s * 16;
            const float4 kv = *(const float4*)(Kp + (size_t)r * QKVDIM + lc);
            Ks[(lc + 0) * 64 + r] = kv.x;
            Ks[(lc + 1) * 64 + r] = kv.y;
            Ks[(lc + 2) * 64 + r] = kv.z;
            Ks[(lc + 3) * 64 + r] = kv.w;
            const float4 vv = *(const float4*)(Vp + (size_t)r * QKVDIM + lc);
            *(float4*)(Vs + r * 64 + lc) = vv;
        }
        __syncthreads();

        float sv[4][4];
        #pragma unroll
        for (int i = 0; i < 4; i++)
            #pragma unroll
            for (int j = 0; j < 4; j++) sv[i][j] = 0.0f;

        #pragma unroll 8
        for (int d = 0; d < 64; d++) {
            const float4 kk = *(const float4*)(Ks + d * 64 + tx * 4);
            const float qa = Qs[(ty * 4 + 0) * 64 + d];
            const float qb = Qs[(ty * 4 + 1) * 64 + d];
            const float qc = Qs[(ty * 4 + 2) * 64 + d];
            const float qd = Qs[(ty * 4 + 3) * 64 + d];
            sv[0][0] += qa * kk.x; sv[0][1] += qa * kk.y; sv[0][2] += qa * kk.z; sv[0][3] += qa * kk.w;
            sv[1][0] += qb * kk.x; sv[1][1] += qb * kk.y; sv[1][2] += qb * kk.z; sv[1][3] += qb * kk.w;
            sv[2][0] += qc * kk.x; sv[2][1] += qc * kk.y; sv[2][2] += qc * kk.z; sv[2][3] += qc * kk.w;
            sv[3][0] += qd * kk.x; sv[3][1] += qd * kk.y; sv[3][2] += qd * kk.z; sv[3][3] += qd * kk.w;
        }

        #pragma unroll
        for (int i = 0; i < 4; i++) {
            float mx = fmaxf(fmaxf(sv[i][0], sv[i][1]), fmaxf(sv[i][2], sv[i][3]));
            mx = fmaxf(mx, __shfl_xor_sync(0xffffffffu, mx, 1, 16));
            mx = fmaxf(mx, __shfl_xor_sync(0xffffffffu, mx, 2, 16));
            mx = fmaxf(mx, __shfl_xor_sync(0xffffffffu, mx, 4, 16));
            mx = fmaxf(mx, __shfl_xor_sync(0xffffffffu, mx, 8, 16));
            const float mnew = fmaxf(m_i[i], mx);
            const float corr = __expf(m_i[i] - mnew);
            m_i[i] = mnew;
            float rs = 0.0f;
            #pragma unroll
            for (int j = 0; j < 4; j++) {
                sv[i][j] = __expf(sv[i][j] - mnew);
                rs += sv[i][j];
            }
            rs += __shfl_xor_sync(0xffffffffu, rs, 1, 16);
            rs += __shfl_xor_sync(0xffffffffu, rs, 2, 16);
            rs += __shfl_xor_sync(0xffffffffu, rs, 4, 16);
            rs += __shfl_xor_sync(0xffffffffu, rs, 8, 16);
            l_i[i] = l_i[i] * corr + rs;
            #pragma unroll
            for (int j = 0; j < 4; j++) acc[i][j] *= corr;
            *(float4*)(Ps + (ty * 4 + i) * 64 + tx * 4) =
                make_float4(sv[i][0], sv[i][1], sv[i][2], sv[i][3]);
        }
        __syncthreads();

        #pragma unroll 8
        for (int k2 = 0; k2 < 64; k2++) {
            const float4 vv = *(const float4*)(Vs + k2 * 64 + tx * 4);
            const float p0 = Ps[(ty * 4 + 0) * 64 + k2];
            const float p1 = Ps[(ty * 4 + 1) * 64 + k2];
            const float p2 = Ps[(ty * 4 + 2) * 64 + k2];
            const float p3 = Ps[(ty * 4 + 3) * 64 + k2];
            acc[0][0] += p0 * vv.x; acc[0][1] += p0 * vv.y; acc[0][2] += p0 * vv.z; acc[0][3] += p0 * vv.w;
            acc[1][0] += p1 * vv.x; acc[1][1] += p1 * vv.y; acc[1][2] += p1 * vv.z; acc[1][3] += p1 * vv.w;
            acc[2][0] += p2 * vv.x; acc[2][1] += p2 * vv.y; acc[2][2] += p2 * vv.z; acc[2][3] += p2 * vv.w;
            acc[3][0] += p3 * vv.x; acc[3][1] += p3 * vv.y; acc[3][2] += p3 * vv.z; acc[3][3] += p3 * vv.w;
        }
        __syncthreads();
    }

    #pragma unroll
    for (int i = 0; i < 4; i++) {
        const float inv = 1.0f / l_i[i];
        const float4 ov = make_float4(acc[i][0] * inv, acc[i][1] * inv,
                                      acc[i][2] * inv, acc[i][3] * inv);
        *(float4*)(o + (size_t)(q0 + ty * 4 + i) * CDIM + h * HDIM + tx * 4) = ov;
    }
}

// ---------------------------------------------------------------------------
// Launcher
// ---------------------------------------------------------------------------
extern "C" void kernel_launch(void* const* d_in, const int* in_sizes, int n_in,
                              void* d_out, int out_size)
{
    const float* x     = (const float*)d_in[0];
    const float* g1    = (const float*)d_in[1];
    const float* g2    = (const float*)d_in[2];
    const float* w_qkv = (const float*)d_in[3];
    const float* w_o   = (const float*)d_in[4];
    const float* w1    = (const float*)d_in[5];
    const float* w2    = (const float*)d_in[6];
    float* out = (float*)d_out;

    float *h, *qkv, *o, *x1, *h2, *t;
    cudaGetSymbolAddress((void**)&h,   g_h);
    cudaGetSymbolAddress((void**)&qkv, g_qkv);
    cudaGetSymbolAddress((void**)&o,   g_o);
    cudaGetSymbolAddress((void**)&x1,  g_x1);
    cudaGetSymbolAddress((void**)&h2,  g_h2);
    cudaGetSymbolAddress((void**)&t,   g_t);

    cudaFuncSetAttribute(flash_kernel,
                         cudaFuncAttributeMaxDynamicSharedMemorySize, 65536);

    // 1) h = rmsnorm(x, g1)
    rmsnorm_kernel<<<NTOK, 256>>>(x, g1, h);

    // 2) qkv = h @ w_qkv          (4096 x 3072, K=1024)
    tgemm_kernel<0><<<dim3(QKVDIM / 128, NTOK / 128), 256>>>(
        h, w_qkv, nullptr, qkv, NTOK, QKVDIM, CDIM);

    // 3) o = attention(qkv)
    flash_kernel<<<dim3(NTOK / 64, NHEAD), 256, 65536>>>(qkv, o);

    // 4) x1 = x + o @ w_o         (4096 x 1024, K=1024)
    tgemm_kernel<1><<<dim3(CDIM / 128, NTOK / 128), 256>>>(
        o, w_o, x, x1, NTOK, CDIM, CDIM);

    // 5) h2 = rmsnorm(x1, g2)
    rmsnorm_kernel<<<NTOK, 256>>>(x1, g2, h2);

    // 6) t = gelu(h2 @ w1)        (4096 x 4096, K=1024)
    tgemm_kernel<2><<<dim3(MDIM / 128, NTOK / 128), 256>>>(
        h2, w1, nullptr, t, NTOK, MDIM, CDIM);

    // 7) out = x1 + t @ w2        (4096 x 1024, K=4096)
    tgemm_kernel<1><<<dim3(CDIM / 128, NTOK / 128), 256>>>(
        t, w2, x1, out, NTOK, CDIM, MDIM);
}

// round 4
// speedup vs baseline: 3.0354x; 1.9755x over previous
#include <cuda_runtime.h>
#include <cuda_bf16.h>
#include <cstdint>

// ---------------------------------------------------------------------------
// Problem constants
// ---------------------------------------------------------------------------
#define NTOK 4096
#define CDIM 1024
#define NHEAD 16
#define HDIM 64
#define MDIM 4096
#define QKVDIM 3072

// ---------------------------------------------------------------------------
// Scratch (device globals — no allocations allowed)
// ---------------------------------------------------------------------------
__device__ float g_h  [(size_t)NTOK * CDIM];    // rmsnorm1 output (tf32-rounded)
__device__ float g_qkv[(size_t)NTOK * QKVDIM];  // qkv (tf32-rounded, q pre-scaled)
__device__ float g_o  [(size_t)NTOK * CDIM];    // attention output (tf32-rounded)
__device__ float g_x1 [(size_t)NTOK * CDIM];    // x + o @ w_o (fp32)
__device__ float g_h2 [(size_t)NTOK * CDIM];    // rmsnorm2 output (tf32-rounded)
__device__ float g_t  [(size_t)NTOK * MDIM];    // gelu(h2 @ w1) (tf32-rounded)
// tf32-rounded weight copies
__device__ float g_wqkv_r[(size_t)CDIM * QKVDIM];
__device__ float g_wo_r  [(size_t)CDIM * CDIM];
__device__ float g_w1_r  [(size_t)CDIM * MDIM];
__device__ float g_w2_r  [(size_t)MDIM * CDIM];

// ---------------------------------------------------------------------------
// Helpers
// ---------------------------------------------------------------------------
__device__ __forceinline__ uint32_t cvt_tf32(float x) {
    uint32_t r;
    asm("cvt.rna.tf32.f32 %0, %1;" : "=r"(r) : "f"(x));
    return r;
}
__device__ __forceinline__ float round_tf32(float x) {
    return __uint_as_float(cvt_tf32(x));
}
__device__ __forceinline__ float gelu_tanh(float x) {
    const float u = 0.7978845608028654f * (x + 0.044715f * x * x * x);
    return 0.5f * x * (1.0f + tanhf(u));
}
__device__ __forceinline__ void mma_tf32(float* c, const uint32_t* a,
                                         const uint32_t* b) {
    asm volatile(
        "mma.sync.aligned.m16n8k8.row.col.f32.tf32.tf32.f32 "
        "{%0,%1,%2,%3}, {%4,%5,%6,%7}, {%8,%9}, {%0,%1,%2,%3};"
        : "+f"(c[0]), "+f"(c[1]), "+f"(c[2]), "+f"(c[3])
        : "r"(a[0]), "r"(a[1]), "r"(a[2]), "r"(a[3]),
          "r"(b[0]), "r"(b[1]));
}
__device__ __forceinline__ void cp16(void* smem, const void* gmem) {
    uint32_t s = (uint32_t)__cvta_generic_to_shared(smem);
    asm volatile("cp.async.cg.shared.global [%0], [%1], 16;"
                 :: "r"(s), "l"(gmem));
}

// ---------------------------------------------------------------------------
// Weight rounding: dst = rna_tf32(src), vectorized
// ---------------------------------------------------------------------------
__global__ __launch_bounds__(256) void round_kernel(
    const float* __restrict__ src, float* __restrict__ dst, int n4)
{
    int i = blockIdx.x * 256 + threadIdx.x;
    if (i >= n4) return;
    float4 v = ((const float4*)src)[i];
    v.x = round_tf32(v.x); v.y = round_tf32(v.y);
    v.z = round_tf32(v.z); v.w = round_tf32(v.w);
    ((float4*)dst)[i] = v;
}

// ---------------------------------------------------------------------------
// RMSNorm: one block per row, output tf32-rounded
// ---------------------------------------------------------------------------
__global__ __launch_bounds__(256) void rmsnorm_kernel(
    const float* __restrict__ x, const float* __restrict__ g,
    float* __restrict__ out)
{
    const int row = blockIdx.x;
    const int tid = threadIdx.x;
    const float4 v = ((const float4*)(x + (size_t)row * CDIM))[tid];
    float ss = v.x * v.x + v.y * v.y + v.z * v.z + v.w * v.w;
    #pragma unroll
    for (int o = 16; o; o >>= 1) ss += __shfl_xor_sync(0xffffffffu, ss, o);
    __shared__ float wsum[8];
    if ((tid & 31) == 0) wsum[tid >> 5] = ss;
    __syncthreads();
    float tot = wsum[0] + wsum[1] + wsum[2] + wsum[3]
              + wsum[4] + wsum[5] + wsum[6] + wsum[7];
    const float inv = rsqrtf(tot * (1.0f / (float)CDIM) + 1e-6f);
    const float4 gv = ((const float4*)g)[tid];
    float4 ov;
    ov.x = round_tf32(v.x * inv * gv.x);
    ov.y = round_tf32(v.y * inv * gv.y);
    ov.z = round_tf32(v.z * inv * gv.z);
    ov.w = round_tf32(v.w * inv * gv.w);
    ((float4*)(out + (size_t)row * CDIM))[tid] = ov;
}

// ---------------------------------------------------------------------------
// TF32 GEMM, inputs already tf32-rounded (raw-bit feed, no cvt in loop)
// MODE 1: C = acc + R (fp32 out)
// MODE 2: C = round(gelu(acc))
// MODE 3: qkv epilogue: scale q columns (<1024) by 0.125, round
// ---------------------------------------------------------------------------
#define AST 20
#define BST 136

template <int MODE>
__global__ __launch_bounds__(256) void tgemm_kernel(
    const float* __restrict__ A, const float* __restrict__ B,
    const float* __restrict__ R, float* __restrict__ C,
    int M, int N, int K)
{
    __shared__ float As[2][128 * AST];
    __shared__ float Bs[2][16 * BST];

    const int tid  = threadIdx.x;
    const int bm   = blockIdx.y * 128;
    const int bn   = blockIdx.x * 128;
    const int warp = tid >> 5;
    const int lane = tid & 31;
    const int wm   = (warp >> 2) << 6;
    const int wn   = (warp & 3) << 5;
    const int lr   = lane >> 2;
    const int lc   = lane & 3;

    float acc[4][4][4];
    #pragma unroll
    for (int mt = 0; mt < 4; mt++)
        #pragma unroll
        for (int nt = 0; nt < 4; nt++)
            #pragma unroll
            for (int i = 0; i < 4; i++) acc[mt][nt][i] = 0.0f;

    auto prefetch = [&](int buf, int k0) {
        #pragma unroll
        for (int r = 0; r < 2; r++) {
            const int idx = tid + (r << 8);
            const int am  = idx >> 2;
            const int akq = (idx & 3) << 2;
            cp16(&As[buf][am * AST + akq],
                 A + (size_t)(bm + am) * K + k0 + akq);
            const int bk  = idx >> 5;
            const int bnq = (idx & 31) << 2;
            cp16(&Bs[buf][bk * BST + bnq],
                 B + (size_t)(k0 + bk) * N + bn + bnq);
        }
        asm volatile("cp.async.commit_group;");
    };

    prefetch(0, 0);
    int buf = 0;

    for (int k0 = 0; k0 < K; k0 += 16) {
        asm volatile("cp.async.wait_group 0;");
        __syncthreads();
        if (k0 + 16 < K) prefetch(buf ^ 1, k0 + 16);

        #pragma unroll
        for (int ks = 0; ks < 2; ks++) {
            uint32_t af[4][4], bf[4][2];
            #pragma unroll
            for (int mt = 0; mt < 4; mt++) {
                const float* ap =
                    &As[buf][(wm + mt * 16 + lr) * AST + ks * 8 + lc];
                af[mt][0] = __float_as_uint(ap[0]);
                af[mt][1] = __float_as_uint(ap[8 * AST]);
                af[mt][2] = __float_as_uint(ap[4]);
                af[mt][3] = __float_as_uint(ap[8 * AST + 4]);
            }
            #pragma unroll
            for (int nt = 0; nt < 4; nt++) {
                const float* bp =
                    &Bs[buf][(ks * 8 + lc) * BST + wn + nt * 8 + lr];
                bf[nt][0] = __float_as_uint(bp[0]);
                bf[nt][1] = __float_as_uint(bp[4 * BST]);
            }
            #pragma unroll
            for (int mt = 0; mt < 4; mt++)
                #pragma unroll
                for (int nt = 0; nt < 4; nt++)
                    mma_tf32(acc[mt][nt], af[mt], bf[nt]);
        }
        __syncthreads();
        buf ^= 1;
    }

    #pragma unroll
    for (int mt = 0; mt < 4; mt++) {
        const int row0 = bm + wm + mt * 16 + lr;
        #pragma unroll
        for (int nt = 0; nt < 4; nt++) {
            const int col = bn + wn + nt * 8 + lc * 2;
            #pragma unroll
            for (int half = 0; half < 2; half++) {
                const size_t row = (size_t)(row0 + half * 8);
                float2 v = make_float2(acc[mt][nt][half * 2],
                                       acc[mt][nt][half * 2 + 1]);
                if (MODE == 1) {
                    const float2 r2 = *(const float2*)(R + row * N + col);
                    v.x += r2.x; v.y += r2.y;
                }
                if (MODE == 2) {
                    v.x = round_tf32(gelu_tanh(v.x));
                    v.y = round_tf32(gelu_tanh(v.y));
                }
                if (MODE == 3) {
                    const float s = (col < CDIM) ? 0.125f : 1.0f;
                    v.x = round_tf32(v.x * s);
                    v.y = round_tf32(v.y * s);
                }
                *(float2*)(C + row * N + col) = v;
            }
        }
    }
}

// ---------------------------------------------------------------------------
// Tensor-core flash attention.
// CTA: 128 threads (4 warps), 64 queries of one head; 64-key tiles.
// qkv pre-rounded to tf32, q pre-scaled by 1/8.
// smem (floats): Qs[64*68] | Ks[2][64*68] | Vs[2][64*72] | Ps[64*68]
// ---------------------------------------------------------------------------
#define QST 68
#define KST 68
#define VST 72
#define FL_SMEM ((4352 + 2*4352 + 2*4608 + 4352) * 4)

__global__ __launch_bounds__(128) void flash_tc_kernel(
    const float* __restrict__ qkv, float* __restrict__ o)
{
    extern __shared__ float sm[];
    float* Qs = sm;                        // 4352
    float* Ks0 = sm + 4352;                // 4352 x2
    float* Vs0 = sm + 4352 + 2 * 4352;     // 4608 x2
    float* Ps = sm + 4352 + 2 * 4352 + 2 * 4608;

    const int tid  = threadIdx.x;
    const int warp = tid >> 5;
    const int lane = tid & 31;
    const int lr   = lane >> 2;
    const int lc   = lane & 3;
    const int h    = blockIdx.y;
    const int q0   = blockIdx.x * 64;

    // Load Q tile (pre-scaled, pre-rounded)
    #pragma unroll
    for (int s = 0; s < 8; s++) {
        const int idx = tid + s * 128;
        const int r  = idx >> 4;
        const int c4 = (idx & 15) << 2;
        const float4 v = *(const float4*)(qkv + (size_t)(q0 + r) * QKVDIM
                                          + h * HDIM + c4);
        *(float4*)(Qs + r * QST + c4) = v;
    }

    auto prefetch = [&](int buf, int k0) {
        float* Kd = Ks0 + buf * 4352;
        float* Vd = Vs0 + buf * 4608;
        const float* Kp = qkv + (size_t)k0 * QKVDIM + CDIM + h * HDIM;
        const float* Vp = Kp + CDIM;
        #pragma unroll
        for (int s = 0; s < 8; s++) {
            const int idx = tid + s * 128;
            const int r  = idx >> 4;
            const int c4 = (idx & 15) << 2;
            cp16(Kd + r * KST + c4, Kp + (size_t)r * QKVDIM + c4);
            cp16(Vd + r * VST + c4, Vp + (size_t)r * QKVDIM + c4);
        }
        asm volatile("cp.async.commit_group;");
    };

    prefetch(0, 0);
    int buf = 0;

    float m0 = -1e30f, m1 = -1e30f, l0 = 0.0f, l1 = 0.0f;
    float oacc[8][4];
    #pragma unroll
    for (int nt = 0; nt < 8; nt++)
        #pragma unroll
        for (int i = 0; i < 4; i++) oacc[nt][i] = 0.0f;

    float* Pw = Ps + (warp * 16) * QST;   // per-warp private P rows

    for (int kt = 0; kt < NTOK / 64; kt++) {
        asm volatile("cp.async.wait_group 0;");
        __syncthreads();
        if (kt + 1 < NTOK / 64) prefetch(buf ^ 1, (kt + 1) * 64);

        const float* Kb = Ks0 + buf * 4352;
        const float* Vb = Vs0 + buf * 4608;

        // --- S = Q K^T (scores already scaled) ---
        float sacc[8][4];
        #pragma unroll
        for (int nt = 0; nt < 8; nt++)
            #pragma unroll
            for (int i = 0; i < 4; i++) sacc[nt][i] = 0.0f;

        #pragma unroll
        for (int ks = 0; ks < 8; ks++) {
            uint32_t af[4];
            const float* ap = Qs + (warp * 16 + lr) * QST + ks * 8 + lc;
            af[0] = __float_as_uint(ap[0]);
            af[1] = __float_as_uint(ap[8 * QST]);
            af[2] = __float_as_uint(ap[4]);
            af[3] = __float_as_uint(ap[8 * QST + 4]);
            #pragma unroll
            for (int nt = 0; nt < 8; nt++) {
                uint32_t bf[2];
                const float* bp = Kb + (nt * 8 + lr) * KST + ks * 8 + lc;
                bf[0] = __float_as_uint(bp[0]);
                bf[1] = __float_as_uint(bp[4]);
                mma_tf32(sacc[nt], af, bf);
            }
        }

        // --- online softmax (rows r0 = warp*16+lr, r1 = r0+8) ---
        {
            float mx0 = -1e30f, mx1 = -1e30f;
            #pragma unroll
            for (int nt = 0; nt < 8; nt++) {
                mx0 = fmaxf(mx0, fmaxf(sacc[nt][0], sacc[nt][1]));
                mx1 = fmaxf(mx1, fmaxf(sacc[nt][2], sacc[nt][3]));
            }
            mx0 = fmaxf(mx0, __shfl_xor_sync(0xffffffffu, mx0, 1));
            mx0 = fmaxf(mx0, __shfl_xor_sync(0xffffffffu, mx0, 2));
            mx1 = fmaxf(mx1, __shfl_xor_sync(0xffffffffu, mx1, 1));
            mx1 = fmaxf(mx1, __shfl_xor_sync(0xffffffffu, mx1, 2));

            const float mn0 = fmaxf(m0, mx0);
            const float mn1 = fmaxf(m1, mx1);
            const float c0 = __expf(m0 - mn0);
            const float c1 = __expf(m1 - mn1);
            m0 = mn0; m1 = mn1;

            float rs0 = 0.0f, rs1 = 0.0f;
            #pragma unroll
            for (int nt = 0; nt < 8; nt++) {
                float p0 = __expf(sacc[nt][0] - mn0);
                float p1 = __expf(sacc[nt][1] - mn0);
                float p2 = __expf(sacc[nt][2] - mn1);
                float p3 = __expf(sacc[nt][3] - mn1);
                rs0 += p0 + p1;
                rs1 += p2 + p3;
                // store tf32-rounded P (per-warp region, no block sync)
                *(float2*)(Pw + lr * QST + nt * 8 + lc * 2) =
                    make_float2(round_tf32(p0), round_tf32(p1));
                *(float2*)(Pw + (lr + 8) * QST + nt * 8 + lc * 2) =
                    make_float2(round_tf32(p2), round_tf32(p3));
                #pragma unroll
                for (int i = 0; i < 2; i++) {
                    oacc[nt][i]     *= c0;
                    oacc[nt][i + 2] *= c1;
                }
            }
            rs0 += __shfl_xor_sync(0xffffffffu, rs0, 1);
            rs0 += __shfl_xor_sync(0xffffffffu, rs0, 2);
            rs1 += __shfl_xor_sync(0xffffffffu, rs1, 1);
            rs1 += __shfl_xor_sync(0xffffffffu, rs1, 2);
            l0 = l0 * c0 + rs0;
            l1 = l1 * c1 + rs1;
        }
        __syncwarp();

        // --- O += P V ---
        #pragma unroll
        for (int ks = 0; ks < 8; ks++) {
            uint32_t af[4];
            const float* ap = Pw + lr * QST + ks * 8 + lc;
            af[0] = __float_as_uint(ap[0]);
            af[1] = __float_as_uint(ap[8 * QST]);
            af[2] = __float_as_uint(ap[4]);
            af[3] = __float_as_uint(ap[8 * QST + 4]);
            #pragma unroll
            for (int nt = 0; nt < 8; nt++) {
                uint32_t bf[2];
                const float* bp = Vb + (ks * 8 + lc) * VST + nt * 8 + lr;
                bf[0] = __float_as_uint(bp[0]);
                bf[1] = __float_as_uint(bp[4 * VST]);
                mma_tf32(oacc[nt], af, bf);
            }
        }
        __syncthreads();
        buf ^= 1;
    }

    // --- write O (tf32-rounded for the w_o GEMM) ---
    const float inv0 = 1.0f / l0;
    const float inv1 = 1.0f / l1;
    const int r0 = q0 + warp * 16 + lr;
    #pragma unroll
    for (int nt = 0; nt < 8; nt++) {
        const int d = nt * 8 + lc * 2;
        *(float2*)(o + (size_t)r0 * CDIM + h * HDIM + d) =
            make_float2(round_tf32(oacc[nt][0] * inv0),
                        round_tf32(oacc[nt][1] * inv0));
        *(float2*)(o + (size_t)(r0 + 8) * CDIM + h * HDIM + d) =
            make_float2(round_tf32(oacc[nt][2] * inv1),
                        round_tf32(oacc[nt][3] * inv1));
    }
}

// ---------------------------------------------------------------------------
// Launcher
// ---------------------------------------------------------------------------
extern "C" void kernel_launch(void* const* d_in, const int* in_sizes, int n_in,
                              void* d_out, int out_size)
{
    const float* x     = (const float*)d_in[0];
    const float* g1    = (const float*)d_in[1];
    const float* g2    = (const float*)d_in[2];
    const float* w_qkv = (const float*)d_in[3];
    const float* w_o   = (const float*)d_in[4];
    const float* w1    = (const float*)d_in[5];
    const float* w2    = (const float*)d_in[6];
    float* out = (float*)d_out;

    float *h, *qkv, *o, *x1, *h2, *t;
    float *wqkv_r, *wo_r, *w1_r, *w2_r;
    cudaGetSymbolAddress((void**)&h,   g_h);
    cudaGetSymbolAddress((void**)&qkv, g_qkv);
    cudaGetSymbolAddress((void**)&o,   g_o);
    cudaGetSymbolAddress((void**)&x1,  g_x1);
    cudaGetSymbolAddress((void**)&h2,  g_h2);
    cudaGetSymbolAddress((void**)&t,   g_t);
    cudaGetSymbolAddress((void**)&wqkv_r, g_wqkv_r);
    cudaGetSymbolAddress((void**)&wo_r,   g_wo_r);
    cudaGetSymbolAddress((void**)&w1_r,   g_w1_r);
    cudaGetSymbolAddress((void**)&w2_r,   g_w2_r);

    cudaFuncSetAttribute(flash_tc_kernel,
                         cudaFuncAttributeMaxDynamicSharedMemorySize, FL_SMEM);

    // 0) round weights to tf32 once per launch
    {
        int n4;
        n4 = (CDIM * QKVDIM) / 4;
        round_kernel<<<(n4 + 255) / 256, 256>>>(w_qkv, wqkv_r, n4);
        n4 = (CDIM * CDIM) / 4;
        round_kernel<<<(n4 + 255) / 256, 256>>>(w_o, wo_r, n4);
        n4 = (CDIM * MDIM) / 4;
        round_kernel<<<(n4 + 255) / 256, 256>>>(w1, w1_r, n4);
        n4 = (MDIM * CDIM) / 4;
        round_kernel<<<(n4 + 255) / 256, 256>>>(w2, w2_r, n4);
    }

    // 1) h = rmsnorm(x, g1)   (tf32-rounded)
    rmsnorm_kernel<<<NTOK, 256>>>(x, g1, h);

    // 2) qkv = h @ w_qkv  (q cols pre-scaled by 1/8, rounded)
    tgemm_kernel<3><<<dim3(QKVDIM / 128, NTOK / 128), 256>>>(
        h, wqkv_r, nullptr, qkv, NTOK, QKVDIM, CDIM);

    // 3) o = attention(qkv)   (tensor-core flash)
    flash_tc_kernel<<<dim3(NTOK / 64, NHEAD), 128, FL_SMEM>>>(qkv, o);

    // 4) x1 = x + o @ w_o
    tgemm_kernel<1><<<dim3(CDIM / 128, NTOK / 128), 256>>>(
        o, wo_r, x, x1, NTOK, CDIM, CDIM);

    // 5) h2 = rmsnorm(x1, g2)   (tf32-rounded)
    rmsnorm_kernel<<<NTOK, 256>>>(x1, g2, h2);

    // 6) t = round(gelu(h2 @ w1))
    tgemm_kernel<2><<<dim3(MDIM / 128, NTOK / 128), 256>>>(
        h2, w1_r, nullptr, t, NTOK, MDIM, CDIM);

    // 7) out = x1 + t @ w2
    tgemm_kernel<1><<<dim3(CDIM / 128, NTOK / 128), 256>>>(
        t, w2_r, x1, out, NTOK, CDIM, MDIM);
}

// round 5
// speedup vs baseline: 7.1549x; 2.3571x over previous
#include <cuda_runtime.h>
#include <cuda_fp16.h>
#include <cstdint>

// ---------------------------------------------------------------------------
// Problem constants
// ---------------------------------------------------------------------------
#define NTOK 4096
#define CDIM 1024
#define NHEAD 16
#define HDIM 64
#define MDIM 4096
#define QKVDIM 3072

// ---------------------------------------------------------------------------
// Scratch (device globals — no allocations allowed)
// ---------------------------------------------------------------------------
__device__ __half g_h  [(size_t)NTOK * CDIM];
__device__ __half g_qkv[(size_t)NTOK * QKVDIM];   // q pre-scaled by 1/8
__device__ __half g_o  [(size_t)NTOK * CDIM];
__device__ float  g_x1 [(size_t)NTOK * CDIM];
__device__ __half g_h2 [(size_t)NTOK * CDIM];
__device__ __half g_t  [(size_t)NTOK * MDIM];
__device__ __half g_wqkv_h[(size_t)CDIM * QKVDIM];
__device__ __half g_wo_h  [(size_t)CDIM * CDIM];
__device__ __half g_w1_h  [(size_t)CDIM * MDIM];
__device__ __half g_w2_h  [(size_t)MDIM * CDIM];

// ---------------------------------------------------------------------------
// Helpers
// ---------------------------------------------------------------------------
__device__ __forceinline__ float gelu_tanh(float x) {
    const float u = 0.7978845608028654f * (x + 0.044715f * x * x * x);
    return 0.5f * x * (1.0f + tanhf(u));
}
__device__ __forceinline__ uint32_t h2u(__half2 v) {
    return *reinterpret_cast<uint32_t*>(&v);
}
__device__ __forceinline__ uint32_t packh2(float a, float b) {
    __half2 v = __floats2half2_rn(a, b);
    return *reinterpret_cast<uint32_t*>(&v);
}
__device__ __forceinline__ void mma_f16(float* c, const uint32_t* a,
                                        const uint32_t* b) {
    asm volatile(
        "mma.sync.aligned.m16n8k16.row.col.f32.f16.f16.f32 "
        "{%0,%1,%2,%3}, {%4,%5,%6,%7}, {%8,%9}, {%0,%1,%2,%3};"
        : "+f"(c[0]), "+f"(c[1]), "+f"(c[2]), "+f"(c[3])
        : "r"(a[0]), "r"(a[1]), "r"(a[2]), "r"(a[3]),
          "r"(b[0]), "r"(b[1]));
}
__device__ __forceinline__ void ldsm4(uint32_t* d, uint32_t a) {
    asm volatile("ldmatrix.sync.aligned.m8n8.x4.shared.b16 "
                 "{%0,%1,%2,%3}, [%4];"
                 : "=r"(d[0]), "=r"(d[1]), "=r"(d[2]), "=r"(d[3]) : "r"(a));
}
__device__ __forceinline__ void ldsm4t(uint32_t* d, uint32_t a) {
    asm volatile("ldmatrix.sync.aligned.m8n8.x4.trans.shared.b16 "
                 "{%0,%1,%2,%3}, [%4];"
                 : "=r"(d[0]), "=r"(d[1]), "=r"(d[2]), "=r"(d[3]) : "r"(a));
}
__device__ __forceinline__ void cp16(void* smem, const void* gmem) {
    uint32_t s = (uint32_t)__cvta_generic_to_shared(smem);
    asm volatile("cp.async.cg.shared.global [%0], [%1], 16;"
                 :: "r"(s), "l"(gmem));
}

// ---------------------------------------------------------------------------
// fp32 -> fp16 weight conversion
// ---------------------------------------------------------------------------
__global__ __launch_bounds__(256) void f2h_kernel(
    const float* __restrict__ src, __half* __restrict__ dst, int n4)
{
    int i = blockIdx.x * 256 + threadIdx.x;
    if (i >= n4) return;
    const float4 v = ((const float4*)src)[i];
    uint2 o;
    o.x = packh2(v.x, v.y);
    o.y = packh2(v.z, v.w);
    ((uint2*)dst)[i] = o;
}

// ---------------------------------------------------------------------------
// RMSNorm: one block per row, fp16 output
// ---------------------------------------------------------------------------
__global__ __launch_bounds__(256) void rmsnorm_kernel(
    const float* __restrict__ x, const float* __restrict__ g,
    __half* __restrict__ out)
{
    const int row = blockIdx.x;
    const int tid = threadIdx.x;
    const float4 v = ((const float4*)(x + (size_t)row * CDIM))[tid];
    float ss = v.x * v.x + v.y * v.y + v.z * v.z + v.w * v.w;
    #pragma unroll
    for (int o = 16; o; o >>= 1) ss += __shfl_xor_sync(0xffffffffu, ss, o);
    __shared__ float wsum[8];
    if ((tid & 31) == 0) wsum[tid >> 5] = ss;
    __syncthreads();
    float tot = wsum[0] + wsum[1] + wsum[2] + wsum[3]
              + wsum[4] + wsum[5] + wsum[6] + wsum[7];
    const float inv = rsqrtf(tot * (1.0f / (float)CDIM) + 1e-6f);
    const float4 gv = ((const float4*)g)[tid];
    uint2 o;
    o.x = packh2(v.x * inv * gv.x, v.y * inv * gv.y);
    o.y = packh2(v.z * inv * gv.z, v.w * inv * gv.w);
    ((uint2*)(out + (size_t)row * CDIM))[tid] = o;
}

// ---------------------------------------------------------------------------
// FP16 tensor-core GEMM: C[M,N] = A[M,K] @ B[K,N], A/B fp16 row-major.
// 128x128x32 tile, 8 warps (warp 64x32), mma.m16n8k16, ldmatrix, cp.async x2.
// MODE 1: float C = acc + R
// MODE 2: half  C = gelu(acc)
// MODE 3: half  C = acc * (col<CDIM ? 0.125 : 1)   (qkv q-scaling)
// ---------------------------------------------------------------------------
#define AHS 40    // A smem row stride (halves): 32 + 8 pad
#define BHS 136   // B smem row stride (halves): 128 + 8 pad

template <int MODE>
__global__ __launch_bounds__(256) void hgemm_kernel(
    const __half* __restrict__ A, const __half* __restrict__ B,
    const float* __restrict__ R, void* __restrict__ Cv,
    int M, int N, int K)
{
    __shared__ __half As[2][128 * AHS];
    __shared__ __half Bs[2][32 * BHS];

    const int tid  = threadIdx.x;
    const int bm   = blockIdx.y * 128;
    const int bn   = blockIdx.x * 128;
    const int warp = tid >> 5;
    const int lane = tid & 31;
    const int wm   = (warp >> 2) << 6;   // 0 / 64
    const int wn   = (warp & 3) << 5;    // 0,32,64,96
    const int lr   = lane >> 2;
    const int lc   = lane & 3;

    float acc[4][4][4];
    #pragma unroll
    for (int mt = 0; mt < 4; mt++)
        #pragma unroll
        for (int nt = 0; nt < 4; nt++)
            #pragma unroll
            for (int i = 0; i < 4; i++) acc[mt][nt][i] = 0.0f;

    auto prefetch = [&](int buf, int k0) {
        #pragma unroll
        for (int r = 0; r < 2; r++) {
            const int c  = tid + (r << 8);          // 0..511
            const int am = c >> 2;                   // 0..127
            const int ak = (c & 3) << 3;             // 0,8,16,24
            cp16(&As[buf][am * AHS + ak],
                 A + (size_t)(bm + am) * K + k0 + ak);
            const int bk = c >> 4;                   // 0..31
            const int bq = (c & 15) << 3;            // 0..120
            cp16(&Bs[buf][bk * BHS + bq],
                 B + (size_t)(k0 + bk) * N + bn + bq);
        }
        asm volatile("cp.async.commit_group;");
    };

    prefetch(0, 0);
    int buf = 0;

    // ldmatrix lane-address components
    const int a_row = lane & 15;
    const int a_hi  = (lane >> 4) << 3;              // 0/8 (k offset)
    const int b_row = (lane & 7) + ((lane >> 3) & 1) * 8;
    const int b_col = (lane >> 4) << 3;              // 0/8 (n offset)

    for (int k0 = 0; k0 < K; k0 += 32) {
        asm volatile("cp.async.wait_group 0;");
        __syncthreads();
        if (k0 + 32 < K) prefetch(buf ^ 1, k0 + 32);

        const uint32_t abase =
            (uint32_t)__cvta_generic_to_shared(&As[buf][0]);
        const uint32_t bbase =
            (uint32_t)__cvta_generic_to_shared(&Bs[buf][0]);

        #pragma unroll
        for (int ks = 0; ks < 2; ks++) {
            uint32_t af[4][4], bf[2][4];
            #pragma unroll
            for (int mt = 0; mt < 4; mt++)
                ldsm4(af[mt], abase + 2 * ((wm + mt * 16 + a_row) * AHS
                                           + ks * 16 + a_hi));
            #pragma unroll
            for (int p = 0; p < 2; p++)
                ldsm4t(bf[p], bbase + 2 * ((ks * 16 + b_row) * BHS
                                           + wn + p * 16 + b_col));
            #pragma unroll
            for (int mt = 0; mt < 4; mt++)
                #pragma unroll
                for (int nt = 0; nt < 4; nt++)
                    mma_f16(acc[mt][nt], af[mt], &bf[nt >> 1][(nt & 1) * 2]);
        }
        __syncthreads();
        buf ^= 1;
    }

    #pragma unroll
    for (int mt = 0; mt < 4; mt++) {
        const int row0 = bm + wm + mt * 16 + lr;
        #pragma unroll
        for (int nt = 0; nt < 4; nt++) {
            const int col = bn + wn + nt * 8 + lc * 2;
            #pragma unroll
            for (int half_ = 0; half_ < 2; half_++) {
                const size_t row = (size_t)(row0 + half_ * 8);
                float vx = acc[mt][nt][half_ * 2];
                float vy = acc[mt][nt][half_ * 2 + 1];
                if (MODE == 1) {
                    const float2 r2 = *(const float2*)(R + row * N + col);
                    float* C = (float*)Cv;
                    *(float2*)(C + row * N + col) =
                        make_float2(vx + r2.x, vy + r2.y);
                } else if (MODE == 2) {
                    __half* C = (__half*)Cv;
                    *(__half2*)(C + row * N + col) =
                        __floats2half2_rn(gelu_tanh(vx), gelu_tanh(vy));
                } else {
                    const float s = (col < CDIM) ? 0.125f : 1.0f;
                    __half* C = (__half*)Cv;
                    *(__half2*)(C + row * N + col) =
                        __floats2half2_rn(vx * s, vy * s);
                }
            }
        }
    }
}

// ---------------------------------------------------------------------------
// FP16 tensor-core flash attention.
// 128 threads (4 warps), 64 queries of one head, 64-key tiles.
// S-fragment registers are repacked directly into PV A-fragments (no smem P).
// ---------------------------------------------------------------------------
#define FHS 72   // smem row stride (halves): 64 + 8 pad

__global__ __launch_bounds__(128) void flash_h_kernel(
    const __half* __restrict__ qkv, __half* __restrict__ o)
{
    __shared__ __half Qs[64 * FHS];
    __shared__ __half Ks[2][64 * FHS];
    __shared__ __half Vs[2][64 * FHS];

    const int tid  = threadIdx.x;
    const int warp = tid >> 5;
    const int lane = tid & 31;
    const int lr   = lane >> 2;
    const int lc   = lane & 3;
    const int hd   = blockIdx.y;
    const int q0   = blockIdx.x * 64;

    // Load Q tile (plain loads; values pre-scaled by 1/8)
    #pragma unroll
    for (int s = 0; s < 4; s++) {
        const int c  = tid + s * 128;
        const int r  = c >> 3;
        const int cq = (c & 7) << 3;
        *(uint4*)(Qs + r * FHS + cq) =
            *(const uint4*)(qkv + (size_t)(q0 + r) * QKVDIM
                            + hd * HDIM + cq);
    }

    auto prefetch = [&](int buf, int k0) {
        const __half* Kp = qkv + (size_t)k0 * QKVDIM + CDIM + hd * HDIM;
        const __half* Vp = Kp + CDIM;
        #pragma unroll
        for (int s = 0; s < 4; s++) {
            const int c  = tid + s * 128;
            const int r  = c >> 3;
            const int cq = (c & 7) << 3;
            cp16(&Ks[buf][r * FHS + cq], Kp + (size_t)r * QKVDIM + cq);
            cp16(&Vs[buf][r * FHS + cq], Vp + (size_t)r * QKVDIM + cq);
        }
        asm volatile("cp.async.commit_group;");
    };

    prefetch(0, 0);
    __syncthreads();   // Qs visible to ldmatrix

    // Hoist Q fragments (constant across key tiles)
    uint32_t qf[4][4];
    {
        const uint32_t qbase = (uint32_t)__cvta_generic_to_shared(Qs);
        const int a_row = warp * 16 + (lane & 15);
        const int a_hi  = (lane >> 4) << 3;
        #pragma unroll
        for (int j = 0; j < 4; j++)
            ldsm4(qf[j], qbase + 2 * (a_row * FHS + j * 16 + a_hi));
    }

    float m0 = -1e30f, m1 = -1e30f, l0 = 0.0f, l1 = 0.0f;
    float oacc[8][4];
    #pragma unroll
    for (int nt = 0; nt < 8; nt++)
        #pragma unroll
        for (int i = 0; i < 4; i++) oacc[nt][i] = 0.0f;

    const int b_row = (lane & 7) + ((lane >> 3) & 1) * 8;  // trans rows
    const int b_col = (lane >> 4) << 3;
    const int k_row = lane & 7;                            // non-trans (K)
    const int k_r2  = ((lane >> 4) & 1) * 8;
    const int k_col = ((lane >> 3) & 1) * 8;

    int buf = 0;
    for (int kt = 0; kt < NTOK / 64; kt++) {
        asm volatile("cp.async.wait_group 0;");
        __syncthreads();
        if (kt + 1 < NTOK / 64) prefetch(buf ^ 1, (kt + 1) * 64);

        const uint32_t kbase =
            (uint32_t)__cvta_generic_to_shared(&Ks[buf][0]);
        const uint32_t vbase =
            (uint32_t)__cvta_generic_to_shared(&Vs[buf][0]);

        // --- S = Q K^T ---
        float sacc[8][4];
        #pragma unroll
        for (int nt = 0; nt < 8; nt++)
            #pragma unroll
            for (int i = 0; i < 4; i++) sacc[nt][i] = 0.0f;

        #pragma unroll
        for (int j = 0; j < 4; j++) {           // k-steps over d
            uint32_t kf[4][4];
            #pragma unroll
            for (int p = 0; p < 4; p++)          // n-tile pairs (keys)
                ldsm4(kf[p], kbase + 2 * ((p * 16 + k_row + k_r2) * FHS
                                          + j * 16 + k_col));
            #pragma unroll
            for (int nt = 0; nt < 8; nt++)
                mma_f16(sacc[nt], qf[j], &kf[nt >> 1][(nt & 1) * 2]);
        }

        // --- online softmax (rows lr and lr+8 of this warp's 16) ---
        float mx0 = -1e30f, mx1 = -1e30f;
        #pragma unroll
        for (int nt = 0; nt < 8; nt++) {
            mx0 = fmaxf(mx0, fmaxf(sacc[nt][0], sacc[nt][1]));
            mx1 = fmaxf(mx1, fmaxf(sacc[nt][2], sacc[nt][3]));
        }
        mx0 = fmaxf(mx0, __shfl_xor_sync(0xffffffffu, mx0, 1));
        mx0 = fmaxf(mx0, __shfl_xor_sync(0xffffffffu, mx0, 2));
        mx1 = fmaxf(mx1, __shfl_xor_sync(0xffffffffu, mx1, 1));
        mx1 = fmaxf(mx1, __shfl_xor_sync(0xffffffffu, mx1, 2));

        const float mn0 = fmaxf(m0, mx0);
        const float mn1 = fmaxf(m1, mx1);
        const float c0 = __expf(m0 - mn0);
        const float c1 = __expf(m1 - mn1);
        m0 = mn0; m1 = mn1;

        float rs0 = 0.0f, rs1 = 0.0f;
        #pragma unroll
        for (int nt = 0; nt < 8; nt++) {
            sacc[nt][0] = __expf(sacc[nt][0] - mn0);
            sacc[nt][1] = __expf(sacc[nt][1] - mn0);
            sacc[nt][2] = __expf(sacc[nt][2] - mn1);
            sacc[nt][3] = __expf(sacc[nt][3] - mn1);
            rs0 += sacc[nt][0] + sacc[nt][1];
            rs1 += sacc[nt][2] + sacc[nt][3];
        }
        rs0 += __shfl_xor_sync(0xffffffffu, rs0, 1);
        rs0 += __shfl_xor_sync(0xffffffffu, rs0, 2);
        rs1 += __shfl_xor_sync(0xffffffffu, rs1, 1);
        rs1 += __shfl_xor_sync(0xffffffffu, rs1, 2);
        l0 = l0 * c0 + rs0;
        l1 = l1 * c1 + rs1;

        #pragma unroll
        for (int nt = 0; nt < 8; nt++) {
            oacc[nt][0] *= c0; oacc[nt][1] *= c0;
            oacc[nt][2] *= c1; oacc[nt][3] *= c1;
        }

        // --- O += P V  (P packed straight from S registers) ---
        #pragma unroll
        for (int j = 0; j < 4; j++) {           // k-steps over keys
            uint32_t pf[4];
            pf[0] = packh2(sacc[2 * j][0],     sacc[2 * j][1]);
            pf[1] = packh2(sacc[2 * j][2],     sacc[2 * j][3]);
            pf[2] = packh2(sacc[2 * j + 1][0], sacc[2 * j + 1][1]);
            pf[3] = packh2(sacc[2 * j + 1][2], sacc[2 * j + 1][3]);
            uint32_t vf[4][4];
            #pragma unroll
            for (int p = 0; p < 4; p++)          // d-tile pairs
                ldsm4t(vf[p], vbase + 2 * ((j * 16 + b_row) * FHS
                                           + p * 16 + b_col));
            #pragma unroll
            for (int nt = 0; nt < 8; nt++)
                mma_f16(oacc[nt], pf, &vf[nt >> 1][(nt & 1) * 2]);
        }
        __syncthreads();
        buf ^= 1;
    }

    // --- write O (fp16 for the w_o GEMM) ---
    const float inv0 = 1.0f / l0;
    const float inv1 = 1.0f / l1;
    const int r0 = q0 + warp * 16 + lr;
    #pragma unroll
    for (int nt = 0; nt < 8; nt++) {
        const int d = nt * 8 + lc * 2;
        *(__half2*)(o + (size_t)r0 * CDIM + hd * HDIM + d) =
            __floats2half2_rn(oacc[nt][0] * inv0, oacc[nt][1] * inv0);
        *(__half2*)(o + (size_t)(r0 + 8) * CDIM + hd * HDIM + d) =
            __floats2half2_rn(oacc[nt][2] * inv1, oacc[nt][3] * inv1);
    }
}

// ---------------------------------------------------------------------------
// Launcher
// ---------------------------------------------------------------------------
extern "C" void kernel_launch(void* const* d_in, const int* in_sizes, int n_in,
                              void* d_out, int out_size)
{
    const float* x     = (const float*)d_in[0];
    const float* g1    = (const float*)d_in[1];
    const float* g2    = (const float*)d_in[2];
    const float* w_qkv = (const float*)d_in[3];
    const float* w_o   = (const float*)d_in[4];
    const float* w1    = (const float*)d_in[5];
    const float* w2    = (const float*)d_in[6];
    float* out = (float*)d_out;

    __half *h, *qkv, *o, *h2, *t;
    __half *wqkv_h, *wo_h, *w1_h, *w2_h;
    float *x1;
    cudaGetSymbolAddress((void**)&h,   g_h);
    cudaGetSymbolAddress((void**)&qkv, g_qkv);
    cudaGetSymbolAddress((void**)&o,   g_o);
    cudaGetSymbolAddress((void**)&x1,  g_x1);
    cudaGetSymbolAddress((void**)&h2,  g_h2);
    cudaGetSymbolAddress((void**)&t,   g_t);
    cudaGetSymbolAddress((void**)&wqkv_h, g_wqkv_h);
    cudaGetSymbolAddress((void**)&wo_h,   g_wo_h);
    cudaGetSymbolAddress((void**)&w1_h,   g_w1_h);
    cudaGetSymbolAddress((void**)&w2_h,   g_w2_h);

    // 0) weights -> fp16 (once per launch)
    {
        int n4;
        n4 = (CDIM * QKVDIM) / 4;
        f2h_kernel<<<(n4 + 255) / 256, 256>>>(w_qkv, wqkv_h, n4);
        n4 = (CDIM * CDIM) / 4;
        f2h_kernel<<<(n4 + 255) / 256, 256>>>(w_o, wo_h, n4);
        n4 = (CDIM * MDIM) / 4;
        f2h_kernel<<<(n4 + 255) / 256, 256>>>(w1, w1_h, n4);
        n4 = (MDIM * CDIM) / 4;
        f2h_kernel<<<(n4 + 255) / 256, 256>>>(w2, w2_h, n4);
    }

    // 1) h = rmsnorm(x, g1)
    rmsnorm_kernel<<<NTOK, 256>>>(x, g1, h);

    // 2) qkv = h @ w_qkv (q scaled by 1/8)
    hgemm_kernel<3><<<dim3(QKVDIM / 128, NTOK / 128), 256>>>(
        h, wqkv_h, nullptr, qkv, NTOK, QKVDIM, CDIM);

    // 3) o = attention(qkv)
    flash_h_kernel<<<dim3(NTOK / 64, NHEAD), 128>>>(qkv, o);

    // 4) x1 = x + o @ w_o
    hgemm_kernel<1><<<dim3(CDIM / 128, NTOK / 128), 256>>>(
        o, wo_h, x, x1, NTOK, CDIM, CDIM);

    // 5) h2 = rmsnorm(x1, g2)
    rmsnorm_kernel<<<NTOK, 256>>>(x1, g2, h2);

    // 6) t = gelu(h2 @ w1)
    hgemm_kernel<2><<<dim3(MDIM / 128, NTOK / 128), 256>>>(
        h2, w1_h, nullptr, t, NTOK, MDIM, CDIM);

    // 7) out = x1 + t @ w2
    hgemm_kernel<1><<<dim3(CDIM / 128, NTOK / 128), 256>>>(
        t, w2_h, x1, out, NTOK, CDIM, MDIM);
}